// round 2
// baseline (speedup 1.0000x reference)
#include <cuda_runtime.h>
#include <math.h>
#include <stdint.h>

// Problem constants
#define BATCH 2
#define NPTS 1024
#define NUM_BINS 22
#define TDIM 16
#define TSTRIDE 20           // padded row stride (floats) to reduce LDS bank conflicts
#define MAX_DIST 40.0f
#define LN_EPS 1e-5f

// Precomputed per-bin output rows: T[bin][d] = relu(LN(W[bin]+b)*gamma+beta)
__device__ float g_table[NUM_BINS * TSTRIDE];

// ---------------------------------------------------------------------------
// Kernel 1: build the 22x16 table (padded stride). One warp, one thread/bin.
// ---------------------------------------------------------------------------
__global__ void build_table_kernel(const float* __restrict__ W,
                                   const float* __restrict__ b,
                                   const float* __restrict__ gamma,
                                   const float* __restrict__ beta) {
    int bin = threadIdx.x;
    if (bin >= NUM_BINS) return;

    float h[TDIM];
    float sum = 0.0f;
#pragma unroll
    for (int d = 0; d < TDIM; ++d) {
        h[d] = W[bin * TDIM + d] + b[d];
        sum += h[d];
    }
    float mu = sum * (1.0f / TDIM);
    float var = 0.0f;
#pragma unroll
    for (int d = 0; d < TDIM; ++d) {
        float c = h[d] - mu;
        var += c * c;
    }
    var *= (1.0f / TDIM);
    float inv = rsqrtf(var + LN_EPS);
#pragma unroll
    for (int d = 0; d < TDIM; ++d) {
        float v = (h[d] - mu) * inv * gamma[d] + beta[d];
        g_table[bin * TSTRIDE + d] = fmaxf(v, 0.0f);
    }
}

// ---------------------------------------------------------------------------
// Kernel 2, two phases per block (one block = one i, 256 j's):
//   Phase A: each thread computes bin-offset (bytes into table) and scale s
//            for ONE j; stashes in smem. (kills the 4x redundant LDG + math)
//   Phase B: 4 lanes per pair; broadcast-read bin/s from smem, gather a
//            float4 from the padded table, 2x packed f32x2 mul, STG.128.
// ---------------------------------------------------------------------------
__global__ __launch_bounds__(256)
void encode_kernel(const float* __restrict__ coords,
                   const float* __restrict__ conf,
                   float* __restrict__ out) {
    __shared__ float sT[NUM_BINS * TSTRIDE];
    __shared__ int   sOff[256];   // byte offset into sT for each local j
    __shared__ float sS[256];     // min(conf_i, conf_j) for each local j

    const int tid   = threadIdx.x;
    const int i     = blockIdx.y;
    const int batch = blockIdx.z;
    const int j_base = blockIdx.x * 256;

    for (int t = tid; t < NUM_BINS * TSTRIDE; t += 256) sT[t] = g_table[t];

    // ---- Phase A: per-j precompute (one thread per j) ----
    {
        const float* ci_ptr = coords + ((size_t)batch * NPTS + i) * 3;
        const float xi = ci_ptr[0], yi = ci_ptr[1], zi = ci_ptr[2];
        const float ci = conf[batch * NPTS + i];

        const int j = j_base + tid;
        const float* cj_ptr = coords + ((size_t)batch * NPTS + j) * 3;
        const float dx = xi - cj_ptr[0];
        const float dy = yi - cj_ptr[1];
        const float dz = zi - cj_ptr[2];
        const float cj = conf[batch * NPTS + j];

        const float dist = sqrtf(fmaf(dx, dx, fmaf(dy, dy, fmaf(dz, dz, 1e-8f))));
        const float inv_w = (float)(NUM_BINS - 1) / MAX_DIST;  // 21/40

        int bin;
        if (ci > 0.0f && cj > 0.0f) {
            bin = (int)(dist * inv_w) + 1;          // #edges strictly below dist
            bin = (bin > NUM_BINS - 2) ? (NUM_BINS - 2) : bin;
        } else {
            bin = NUM_BINS - 1;
        }
        sOff[tid] = bin * (TSTRIDE * 4);            // byte offset of table row
        sS[tid]   = fminf(ci, cj);
    }
    __syncthreads();

    // ---- Phase B: gather + scale + store ----
    const int p = tid >> 2;   // pair slot within 64
    const int k = tid & 3;    // which float4 of the 16-vector

    // per-thread store pointer; advances 64 j's (4096 floats) per iter
    float* optr = out + (((size_t)batch * NPTS + i) * NPTS + j_base + p) * TDIM + k * 4;
    const char* tbase = (const char*)sT + k * 16;

#pragma unroll
    for (int it = 0; it < 4; ++it) {
        const int jl = it * 64 + p;
        const int off = sOff[jl];        // broadcast within the 4-lane group
        const float s = sS[jl];

        float4 v = *(const float4*)(tbase + off);

        // packed f32x2 multiplies: 2 instructions instead of 4
        uint64_t lo, hi, sv, rlo, rhi;
        asm("mov.b64 %0, {%1, %2};" : "=l"(sv) : "f"(s), "f"(s));
        asm("mov.b64 %0, {%1, %2};" : "=l"(lo) : "f"(v.x), "f"(v.y));
        asm("mov.b64 %0, {%1, %2};" : "=l"(hi) : "f"(v.z), "f"(v.w));
        asm("mul.rn.f32x2 %0, %1, %2;" : "=l"(rlo) : "l"(lo), "l"(sv));
        asm("mul.rn.f32x2 %0, %1, %2;" : "=l"(rhi) : "l"(hi), "l"(sv));
        float4 r;
        asm("mov.b64 {%0, %1}, %2;" : "=f"(r.x), "=f"(r.y) : "l"(rlo));
        asm("mov.b64 {%0, %1}, %2;" : "=f"(r.z), "=f"(r.w) : "l"(rhi));

        *(float4*)(optr + (size_t)it * 64 * TDIM) = r;
    }
}

// ---------------------------------------------------------------------------
// Launch
// ---------------------------------------------------------------------------
extern "C" void kernel_launch(void* const* d_in, const int* in_sizes, int n_in,
                              void* d_out, int out_size) {
    const float* coords = (const float*)d_in[0];  // (B,N,3)
    const float* conf   = (const float*)d_in[1];  // (B,N)
    const float* W      = (const float*)d_in[2];  // (22,16)
    const float* b      = (const float*)d_in[3];  // (16,)
    const float* gamma  = (const float*)d_in[4];  // (16,)
    const float* beta   = (const float*)d_in[5];  // (16,)
    float* out = (float*)d_out;                   // (B,N,N,16)

    build_table_kernel<<<1, 32>>>(W, b, gamma, beta);

    dim3 grid(NPTS / 256, NPTS, BATCH);
    encode_kernel<<<grid, 256>>>(coords, conf, out);
}